// round 8
// baseline (speedup 1.0000x reference)
#include <cuda_runtime.h>
#include <cuda_fp16.h>
#include <stdint.h>

#define BB 4
#define LL 4096
#define DD 256
#define AA 64
#define INFF 1e30f
#define LOG2E 1.4426950408889634f

// ------------------------- fp16 split scratch ------------------------------
__device__ __align__(256) __half g_qhi[BB * LL * AA];
__device__ __align__(256) __half g_qlo[BB * LL * AA];
__device__ __align__(256) __half g_khi[BB * LL * AA];  // pre-scaled by log2e
__device__ __align__(256) __half g_klo[BB * LL * AA];
__device__ __align__(256) __half g_vhi[BB * LL * AA];  // single fp16

// ------------------------- PTX helpers -------------------------------------
__device__ __forceinline__ uint32_t smem_u32(const void* p) {
    uint32_t a;
    asm("{ .reg .u64 t; cvta.to.shared.u64 t, %1; cvt.u32.u64 %0, t; }"
        : "=r"(a) : "l"(p));
    return a;
}

#define SWZI(r, c4) (((r) << 7) + ((((c4) ^ ((r) & 7))) << 4))

__device__ __forceinline__ void ldsm4(unsigned r[4], uint32_t a) {
    asm volatile("ldmatrix.sync.aligned.m8n8.x4.shared.b16 {%0,%1,%2,%3}, [%4];"
        : "=r"(r[0]), "=r"(r[1]), "=r"(r[2]), "=r"(r[3]) : "r"(a));
}
__device__ __forceinline__ void ldsm4t(unsigned r[4], uint32_t a) {
    asm volatile("ldmatrix.sync.aligned.m8n8.x4.trans.shared.b16 {%0,%1,%2,%3}, [%4];"
        : "=r"(r[0]), "=r"(r[1]), "=r"(r[2]), "=r"(r[3]) : "r"(a));
}
__device__ __forceinline__ void mma16816(float d[4], const unsigned a[4],
                                         const unsigned b[2]) {
    asm volatile("mma.sync.aligned.m16n8k16.row.col.f32.f16.f16.f32 "
        "{%0,%1,%2,%3}, {%4,%5,%6,%7}, {%8,%9}, {%0,%1,%2,%3};"
        : "+f"(d[0]), "+f"(d[1]), "+f"(d[2]), "+f"(d[3])
        : "r"(a[0]), "r"(a[1]), "r"(a[2]), "r"(a[3]), "r"(b[0]), "r"(b[1]));
}
#define CP16(d, s) asm volatile("cp.async.cg.shared.global [%0], [%1], 16;" :: "r"(d), "l"(s))
#define CP_COMMIT() asm volatile("cp.async.commit_group;" ::: "memory")
#define CP_WAIT0()  asm volatile("cp.async.wait_group 0;" ::: "memory")

__device__ __forceinline__ float ex2f(float x) {
    float r;
    asm("ex2.approx.ftz.f32 %0, %1;" : "=f"(r) : "f"(x));
    return r;
}
// pack hi fp16x2, return lo residual fp16x2 via out-param
__device__ __forceinline__ unsigned pkhl(float a, float b, unsigned& lo) {
    __half2 h2 = __floats2half2_rn(a, b);
    float2 hf = __half22float2(h2);
    __half2 l2 = __floats2half2_rn(a - hf.x, b - hf.y);
    lo = *(unsigned*)&l2;
    return *(unsigned*)&h2;
}

// ---------------------------------------------------------------------------
// Kernel 1: QKV projection on tensor cores (fp16 3-pass split).
// CTA = 64 output rows x 192 cols, 4 warps (warp = 16 rows x 192 cols).
// x and W tiles converted to fp16 hi/lo in smem per 64-d chunk.
// ---------------------------------------------------------------------------
#define PSM_XH 0        // x hi: 64 x 64 fp16, SW128 rows
#define PSM_XL 8192
#define PSM_WH 16384    // W hi: 3 mats x (64d x 64a)
#define PSM_WL 40960
#define PSM_TOTAL 65536

extern __shared__ char smc[];

__global__ __launch_bounds__(128) void qkv_proj_kernel(
    const float* __restrict__ x,
    const float* __restrict__ Wq,
    const float* __restrict__ Wk,
    const float* __restrict__ Wv)
{
    const uint32_t sb = smem_u32(smc);
    const int t    = threadIdx.x;
    const int w    = t >> 5;
    const int lane = t & 31;
    const int m0   = blockIdx.x * 64;

    float acc[3][8][4];
#pragma unroll
    for (int m = 0; m < 3; m++)
#pragma unroll
        for (int nt = 0; nt < 8; nt++)
#pragma unroll
            for (int e = 0; e < 4; e++) acc[m][nt][e] = 0.f;

    for (int d0 = 0; d0 < DD; d0 += 64) {
        __syncthreads();   // previous chunk's ldsm reads complete

        // Convert x tile (64 rows x 64 d) to fp16 hi/lo.
#pragma unroll
        for (int i = 0; i < 4; i++) {
            int idx = t + i * 128;         // 0..511 16B-chunks
            int r  = idx >> 3;
            int c4 = idx & 7;
            const float* src = &x[(size_t)(m0 + r) * DD + d0 + c4 * 8];
            float4 f0 = *(const float4*)&src[0];
            float4 f1 = *(const float4*)&src[4];
            uint4 hi, lo;
            hi.x = pkhl(f0.x, f0.y, lo.x);
            hi.y = pkhl(f0.z, f0.w, lo.y);
            hi.z = pkhl(f1.x, f1.y, lo.z);
            hi.w = pkhl(f1.z, f1.w, lo.w);
            int so = SWZI(r, c4);
            *(uint4*)(smc + PSM_XH + so) = hi;
            *(uint4*)(smc + PSM_XL + so) = lo;
        }
        // Convert W chunk (rows d0..d0+63, 3 mats x 64 cols). Wk scaled log2e.
#pragma unroll
        for (int i = 0; i < 12; i++) {
            int idx = t + i * 128;         // 0..1535
            int mat = idx >> 9;
            int rr  = idx & 511;
            int r   = rr >> 3;
            int c4  = rr & 7;
            const float* W = (mat == 0) ? Wq : (mat == 1) ? Wk : Wv;
            const float* src = &W[(size_t)(d0 + r) * AA + c4 * 8];
            float s = (mat == 1) ? LOG2E : 1.f;
            float4 f0 = *(const float4*)&src[0];
            float4 f1 = *(const float4*)&src[4];
            uint4 hi, lo;
            hi.x = pkhl(f0.x * s, f0.y * s, lo.x);
            hi.y = pkhl(f0.z * s, f0.w * s, lo.y);
            hi.z = pkhl(f1.x * s, f1.y * s, lo.z);
            hi.w = pkhl(f1.z * s, f1.w * s, lo.w);
            int so = mat * 8192 + SWZI(r, c4);
            *(uint4*)(smc + PSM_WH + so) = hi;
            *(uint4*)(smc + PSM_WL + so) = lo;
        }
        __syncthreads();

        // GEMM: 3 split passes (xh*wh + xl*wh + xh*wl).
#pragma unroll
        for (int kt = 0; kt < 4; kt++) {
            unsigned ah[4], al[4];
            uint32_t qa = sb + PSM_XH +
                SWZI(w * 16 + (lane & 15), kt * 2 + (lane >> 4));
            ldsm4(ah, qa);
            ldsm4(al, qa + 8192);
#pragma unroll
            for (int mat = 0; mat < 3; mat++) {
#pragma unroll
                for (int c4t = 0; c4t < 4; c4t++) {
                    int r  = kt * 16 + (((lane >> 3) & 1) << 3) + (lane & 7);
                    int c4 = c4t * 2 + (lane >> 4);
                    unsigned bh[4], bl[4];
                    ldsm4t(bh, sb + PSM_WH + mat * 8192 + SWZI(r, c4));
                    ldsm4t(bl, sb + PSM_WL + mat * 8192 + SWZI(r, c4));
#pragma unroll
                    for (int ntl = 0; ntl < 2; ntl++)
                        mma16816(acc[mat][c4t * 2 + ntl], ah, bh + 2 * ntl);
#pragma unroll
                    for (int ntl = 0; ntl < 2; ntl++)
                        mma16816(acc[mat][c4t * 2 + ntl], al, bh + 2 * ntl);
#pragma unroll
                    for (int ntl = 0; ntl < 2; ntl++)
                        mma16816(acc[mat][c4t * 2 + ntl], ah, bl + 2 * ntl);
                }
            }
        }
    }

    // Epilogue: split to fp16 hi/lo (q,k) / single fp16 (v), store.
    const int g  = lane >> 2;
    const int tq = lane & 3;
    const size_t r0 = (size_t)(m0 + w * 16 + g);
    const size_t r1 = r0 + 8;
#pragma unroll
    for (int nt = 0; nt < 8; nt++) {
        int c = nt * 8 + 2 * tq;
        // q
        {
            unsigned lo0, lo1;
            unsigned h0 = pkhl(acc[0][nt][0], acc[0][nt][1], lo0);
            unsigned h1 = pkhl(acc[0][nt][2], acc[0][nt][3], lo1);
            *(unsigned*)&g_qhi[r0 * AA + c] = h0;
            *(unsigned*)&g_qlo[r0 * AA + c] = lo0;
            *(unsigned*)&g_qhi[r1 * AA + c] = h1;
            *(unsigned*)&g_qlo[r1 * AA + c] = lo1;
        }
        // k (already log2e-scaled via Wk)
        {
            unsigned lo0, lo1;
            unsigned h0 = pkhl(acc[1][nt][0], acc[1][nt][1], lo0);
            unsigned h1 = pkhl(acc[1][nt][2], acc[1][nt][3], lo1);
            *(unsigned*)&g_khi[r0 * AA + c] = h0;
            *(unsigned*)&g_klo[r0 * AA + c] = lo0;
            *(unsigned*)&g_khi[r1 * AA + c] = h1;
            *(unsigned*)&g_klo[r1 * AA + c] = lo1;
        }
        // v (single fp16)
        {
            __half2 v0 = __floats2half2_rn(acc[2][nt][0], acc[2][nt][1]);
            __half2 v1 = __floats2half2_rn(acc[2][nt][2], acc[2][nt][3]);
            *(__half2*)&g_vhi[r0 * AA + c] = v0;
            *(__half2*)&g_vhi[r1 * AA + c] = v1;
        }
    }
}

// ---------------------------------------------------------------------------
// Kernel 2: causal flash attention via fp16 mma.sync (unchanged from R7).
// ---------------------------------------------------------------------------
#define SM_QH  0
#define SM_QL  8192
#define SM_KH  16384   // 2 bufs x 8KB
#define SM_KL  32768
#define SM_VH  49152
#define SM_TOTAL 65536

__device__ __forceinline__ void prefetch_kv(uint32_t sb, int buf, size_t gkb, int t)
{
#pragma unroll
    for (int i = 0; i < 4; i++) {
        int idx = t + i * 128;          // 0..511
        int r  = idx >> 3;
        int c4 = idx & 7;
        size_t g = gkb + (size_t)r * AA + c4 * 8;
        uint32_t so = (uint32_t)(buf * 8192 + SWZI(r, c4));
        CP16(sb + SM_KH + so, g_khi + g);
        CP16(sb + SM_KL + so, g_klo + g);
        CP16(sb + SM_VH + so, g_vhi + g);
    }
}

__global__ __launch_bounds__(128, 2) void attn_kernel(float* __restrict__ out)
{
    const uint32_t sb = smem_u32(smc);
    const int t    = threadIdx.x;
    const int w    = t >> 5;
    const int lane = t & 31;

    // bid -> (tile, b): SM-pair (bid, bid+148) loads sum to 65 or 55 steps;
    // single-CTA SMs (bids 108..147) get mid tiles (41..50 steps).
    const int bid = blockIdx.x;
    int tile, b;
    if (bid < 56)       { tile = bid >> 2;              b = bid & 3; }
    else if (bid < 108) { tile = 14 + ((bid - 56) >> 2); b = (bid - 56) & 3; }
    else if (bid < 148) { tile = 40 + ((bid - 108) >> 2); b = (bid - 108) & 3; }
    else if (bid < 204) { tile = 63 - ((bid - 148) >> 2); b = (bid - 148) & 3; }
    else                { tile = 39 - ((bid - 204) >> 2); b = (bid - 204) & 3; }

    const size_t gbase = (size_t)b * LL * AA;
    const int rb = tile * 64 + w * 16;

    prefetch_kv(sb, 0, gbase, t);
    CP_COMMIT();

    // Load Q tile (64 rows x 64 fp16, hi+lo).
#pragma unroll
    for (int i = 0; i < 4; i++) {
        int idx = t + i * 128;
        int r  = idx >> 3;
        int c4 = idx & 7;
        size_t g = gbase + (size_t)(tile * 64 + r) * AA + c4 * 8;
        int so = SWZI(r, c4);
        *(uint4*)(smc + SM_QH + so) = *(const uint4*)&g_qhi[g];
        *(uint4*)(smc + SM_QL + so) = *(const uint4*)&g_qlo[g];
    }

    float O[8][4];
    float mr[2], lr[2];
    mr[0] = mr[1] = -INFF;
    lr[0] = lr[1] = 0.f;
#pragma unroll
    for (int nt = 0; nt < 8; nt++)
#pragma unroll
        for (int e = 0; e < 4; e++) O[nt][e] = 0.f;

    const int g  = lane >> 2;
    const int tq = lane & 3;

    for (int jt = 0; jt <= tile; jt++) {
        const int buf = jt & 1;
        CP_WAIT0();
        __syncthreads();
        if (jt < tile) {
            prefetch_kv(sb, buf ^ 1, gbase + (size_t)(jt + 1) * 64 * AA, t);
            CP_COMMIT();
        }
        const int kb = jt * 64;
        const bool diag = (jt == tile);

        float S[8][4];
#pragma unroll
        for (int nt = 0; nt < 8; nt++)
#pragma unroll
            for (int e = 0; e < 4; e++) S[nt][e] = 0.f;

        const uint32_t khb = sb + SM_KH + buf * 8192;
        const uint32_t klb = sb + SM_KL + buf * 8192;

        // ---- S = Q K^T (3 split passes) ----
#pragma unroll
        for (int kt = 0; kt < 4; kt++) {
            unsigned qh4[4], ql4[4];
            uint32_t qa = sb + SM_QH +
                SWZI(w * 16 + (lane & 15), kt * 2 + (lane >> 4));
            ldsm4(qh4, qa);
            ldsm4(ql4, qa + 8192);
#pragma unroll
            for (int np = 0; np < 4; np++) {
                int r  = np * 16 + ((lane >> 4) << 3) + (lane & 7);
                int c4 = kt * 2 + ((lane >> 3) & 1);
                unsigned kh4[4], kl4[4];
                ldsm4(kh4, khb + SWZI(r, c4));
                ldsm4(kl4, klb + SWZI(r, c4));
#pragma unroll
                for (int ntl = 0; ntl < 2; ntl++)
                    mma16816(S[2 * np + ntl], qh4, kh4 + 2 * ntl);
#pragma unroll
                for (int ntl = 0; ntl < 2; ntl++)
                    mma16816(S[2 * np + ntl], ql4, kh4 + 2 * ntl);
#pragma unroll
                for (int ntl = 0; ntl < 2; ntl++)
                    mma16816(S[2 * np + ntl], qh4, kl4 + 2 * ntl);
            }
        }

        // ---- mask + row max + O rescale ----
        int r0 = rb + g, r1 = r0 + 8;
        if (diag) {
#pragma unroll
            for (int nt = 0; nt < 8; nt++) {
                int col = kb + nt * 8 + 2 * tq;
                if (col     > r0) S[nt][0] = -INFF;
                if (col + 1 > r0) S[nt][1] = -INFF;
                if (col     > r1) S[nt][2] = -INFF;
                if (col + 1 > r1) S[nt][3] = -INFF;
            }
        }
        float m0 = -INFF, m1 = -INFF;
#pragma unroll
        for (int nt = 0; nt < 8; nt++) {
            m0 = fmaxf(m0, fmaxf(S[nt][0], S[nt][1]));
            m1 = fmaxf(m1, fmaxf(S[nt][2], S[nt][3]));
        }
        m0 = fmaxf(m0, __shfl_xor_sync(0xffffffffu, m0, 1));
        m0 = fmaxf(m0, __shfl_xor_sync(0xffffffffu, m0, 2));
        m1 = fmaxf(m1, __shfl_xor_sync(0xffffffffu, m1, 1));
        m1 = fmaxf(m1, __shfl_xor_sync(0xffffffffu, m1, 2));
        float mn0 = fmaxf(mr[0], m0), mn1 = fmaxf(mr[1], m1);
        float sc0 = ex2f(mr[0] - mn0), sc1 = ex2f(mr[1] - mn1);
        mr[0] = mn0; mr[1] = mn1;
#pragma unroll
        for (int nt = 0; nt < 8; nt++) {
            O[nt][0] *= sc0; O[nt][1] *= sc0;
            O[nt][2] *= sc1; O[nt][3] *= sc1;
        }

        // ---- exp/pack interleaved with PV (P split in regs, V single) ----
        const uint32_t vhb = sb + SM_VH + buf * 8192;
        float rs0 = 0.f, rs1 = 0.f;
#pragma unroll
        for (int kt = 0; kt < 4; kt++) {
            unsigned ph[4], pl[4];
            {
                float e00 = ex2f(S[2*kt  ][0] - mn0);
                float e01 = ex2f(S[2*kt  ][1] - mn0);
                float e02 = ex2f(S[2*kt  ][2] - mn1);
                float e03 = ex2f(S[2*kt  ][3] - mn1);
                float e10 = ex2f(S[2*kt+1][0] - mn0);
                float e11 = ex2f(S[2*kt+1][1] - mn0);
                float e12 = ex2f(S[2*kt+1][2] - mn1);
                float e13 = ex2f(S[2*kt+1][3] - mn1);
                rs0 += (e00 + e01) + (e10 + e11);
                rs1 += (e02 + e03) + (e12 + e13);
                ph[0] = pkhl(e00, e01, pl[0]);
                ph[1] = pkhl(e02, e03, pl[1]);
                ph[2] = pkhl(e10, e11, pl[2]);
                ph[3] = pkhl(e12, e13, pl[3]);
            }
#pragma unroll
            for (int np = 0; np < 4; np++) {
                int r  = kt * 16 + (((lane >> 3) & 1) << 3) + (lane & 7);
                int c4 = np * 2 + (lane >> 4);
                unsigned vh4[4];
                ldsm4t(vh4, vhb + SWZI(r, c4));
#pragma unroll
                for (int ntl = 0; ntl < 2; ntl++)
                    mma16816(O[2 * np + ntl], ph, vh4 + 2 * ntl);
#pragma unroll
                for (int ntl = 0; ntl < 2; ntl++)
                    mma16816(O[2 * np + ntl], pl, vh4 + 2 * ntl);
            }
        }

        rs0 += __shfl_xor_sync(0xffffffffu, rs0, 1);
        rs0 += __shfl_xor_sync(0xffffffffu, rs0, 2);
        rs1 += __shfl_xor_sync(0xffffffffu, rs1, 1);
        rs1 += __shfl_xor_sync(0xffffffffu, rs1, 2);
        lr[0] = lr[0] * sc0 + rs0;
        lr[1] = lr[1] * sc1 + rs1;

        __syncthreads();
    }

    // ---- epilogue ----
    float i0 = 1.f / lr[0], i1 = 1.f / lr[1];
    size_t r0 = (size_t)(rb + g), r1 = r0 + 8;
#pragma unroll
    for (int nt = 0; nt < 8; nt++) {
        *(float2*)&out[gbase + r0 * AA + nt * 8 + 2 * tq] =
            make_float2(O[nt][0] * i0, O[nt][1] * i0);
        *(float2*)&out[gbase + r1 * AA + nt * 8 + 2 * tq] =
            make_float2(O[nt][2] * i1, O[nt][3] * i1);
    }
}

// ---------------------------------------------------------------------------
extern "C" void kernel_launch(void* const* d_in, const int* in_sizes, int n_in,
                              void* d_out, int out_size)
{
    const float* x  = (const float*)d_in[0];
    const float* Wq = (const float*)d_in[1];
    const float* Wk = (const float*)d_in[2];
    const float* Wv = (const float*)d_in[3];
    float* out = (float*)d_out;

    cudaFuncSetAttribute(qkv_proj_kernel,
                         cudaFuncAttributeMaxDynamicSharedMemorySize, PSM_TOTAL);
    qkv_proj_kernel<<<BB * LL / 64, 128, PSM_TOTAL>>>(x, Wq, Wk, Wv);

    cudaFuncSetAttribute(attn_kernel,
                         cudaFuncAttributeMaxDynamicSharedMemorySize, SM_TOTAL);
    attn_kernel<<<256, 128, SM_TOTAL>>>(out);
}

// round 9
// speedup vs baseline: 1.2389x; 1.2389x over previous
#include <cuda_runtime.h>
#include <cuda_fp16.h>
#include <stdint.h>

#define BB 4
#define LL 4096
#define DD 256
#define AA 64
#define INFF 1e30f
#define LOG2E 1.4426950408889634f

typedef unsigned long long ull;

// ------------------------- fp16 split scratch ------------------------------
__device__ __align__(256) __half g_qhi[BB * LL * AA];
__device__ __align__(256) __half g_qlo[BB * LL * AA];
__device__ __align__(256) __half g_khi[BB * LL * AA];  // pre-scaled by log2e
__device__ __align__(256) __half g_klo[BB * LL * AA];
__device__ __align__(256) __half g_vhi[BB * LL * AA];  // single fp16

// ------------------------- PTX helpers -------------------------------------
__device__ __forceinline__ uint32_t smem_u32(const void* p) {
    uint32_t a;
    asm("{ .reg .u64 t; cvta.to.shared.u64 t, %1; cvt.u32.u64 %0, t; }"
        : "=r"(a) : "l"(p));
    return a;
}

#define SWZI(r, c4) (((r) << 7) + ((((c4) ^ ((r) & 7))) << 4))

__device__ __forceinline__ void ldsm4(unsigned r[4], uint32_t a) {
    asm volatile("ldmatrix.sync.aligned.m8n8.x4.shared.b16 {%0,%1,%2,%3}, [%4];"
        : "=r"(r[0]), "=r"(r[1]), "=r"(r[2]), "=r"(r[3]) : "r"(a));
}
__device__ __forceinline__ void ldsm4t(unsigned r[4], uint32_t a) {
    asm volatile("ldmatrix.sync.aligned.m8n8.x4.trans.shared.b16 {%0,%1,%2,%3}, [%4];"
        : "=r"(r[0]), "=r"(r[1]), "=r"(r[2]), "=r"(r[3]) : "r"(a));
}
__device__ __forceinline__ void mma16816(float d[4], const unsigned a[4],
                                         const unsigned b[2]) {
    asm volatile("mma.sync.aligned.m16n8k16.row.col.f32.f16.f16.f32 "
        "{%0,%1,%2,%3}, {%4,%5,%6,%7}, {%8,%9}, {%0,%1,%2,%3};"
        : "+f"(d[0]), "+f"(d[1]), "+f"(d[2]), "+f"(d[3])
        : "r"(a[0]), "r"(a[1]), "r"(a[2]), "r"(a[3]), "r"(b[0]), "r"(b[1]));
}
#define CP16(d, s) asm volatile("cp.async.cg.shared.global [%0], [%1], 16;" :: "r"(d), "l"(s))
#define CP_COMMIT() asm volatile("cp.async.commit_group;" ::: "memory")
#define CP_WAIT0()  asm volatile("cp.async.wait_group 0;" ::: "memory")

__device__ __forceinline__ float ex2f(float x) {
    float r;
    asm("ex2.approx.ftz.f32 %0, %1;" : "=f"(r) : "f"(x));
    return r;
}
__device__ __forceinline__ ull pk2(float a) {
    ull r; unsigned u = __float_as_uint(a);
    asm("mov.b64 %0, {%1, %1};" : "=l"(r) : "r"(u));
    return r;
}
__device__ __forceinline__ void fma2(ull& d, ull a, ull b) {
    asm("fma.rn.f32x2 %0, %1, %2, %0;" : "+l"(d) : "l"(a), "l"(b));
}
__device__ __forceinline__ void upk(ull v, float& x, float& y) {
    unsigned a, b;
    asm("mov.b64 {%0, %1}, %2;" : "=r"(a), "=r"(b) : "l"(v));
    x = __uint_as_float(a); y = __uint_as_float(b);
}
// pack hi fp16x2, return lo residual fp16x2 via out-param
__device__ __forceinline__ unsigned pkhl(float a, float b, unsigned& lo) {
    __half2 h2 = __floats2half2_rn(a, b);
    float2 hf = __half22float2(h2);
    __half2 l2 = __floats2half2_rn(a - hf.x, b - hf.y);
    lo = *(unsigned*)&l2;
    return *(unsigned*)&h2;
}

// ---------------------------------------------------------------------------
// Kernel 1: fused QKV projection (f32x2 inner loop) -> fp16 splits.
// (Reverted to R7 version: measured-good.)
// ---------------------------------------------------------------------------
__global__ __launch_bounds__(256) void qkv_proj_kernel(
    const float* __restrict__ x,
    const float* __restrict__ Wq,
    const float* __restrict__ Wk,
    const float* __restrict__ Wv)
{
    __shared__ float xs[32 * 65];
    __shared__ float ws[32 * 196];

    const int t  = threadIdx.x;
    const int ty = t >> 4;
    const int tx = t & 15;
    const int m0 = blockIdx.x * 64;

    ull acc2[4][6];
#pragma unroll
    for (int i = 0; i < 4; i++)
#pragma unroll
        for (int j = 0; j < 6; j++) acc2[i][j] = 0ull;

    for (int d0 = 0; d0 < DD; d0 += 32) {
#pragma unroll
        for (int i = 0; i < 8; i++) {
            int idx = t + i * 256;
            int m = idx >> 5;
            int d = idx & 31;
            xs[d * 65 + m] = x[(size_t)(m0 + m) * DD + d0 + d];
        }
#pragma unroll
        for (int i = 0; i < 6; i++) {
            int idx = t + i * 256;
            int mat = idx >> 9;
            int r   = idx & 511;
            int d   = r >> 4;
            int a4  = r & 15;
            const float* W = (mat == 0) ? Wq : (mat == 1) ? Wk : Wv;
            *(float4*)&ws[d * 196 + mat * 64 + a4 * 4] =
                *(const float4*)&W[(size_t)(d0 + d) * AA + a4 * 4];
        }
        __syncthreads();

#pragma unroll
        for (int d = 0; d < 32; d++) {
            ull ap[4];
#pragma unroll
            for (int i = 0; i < 4; i++) ap[i] = pk2(xs[d * 65 + ty * 4 + i]);
            const ull* bq = (const ull*)&ws[d * 196 +       tx * 4];
            const ull* bk = (const ull*)&ws[d * 196 +  64 + tx * 4];
            const ull* bv = (const ull*)&ws[d * 196 + 128 + tx * 4];
            ull q0 = bq[0], q1 = bq[1];
            ull k0 = bk[0], k1 = bk[1];
            ull v0 = bv[0], v1 = bv[1];
#pragma unroll
            for (int i = 0; i < 4; i++) {
                fma2(acc2[i][0], ap[i], q0); fma2(acc2[i][1], ap[i], q1);
                fma2(acc2[i][2], ap[i], k0); fma2(acc2[i][3], ap[i], k1);
                fma2(acc2[i][4], ap[i], v0); fma2(acc2[i][5], ap[i], v1);
            }
        }
        __syncthreads();
    }

#pragma unroll
    for (int i = 0; i < 4; i++) {
        size_t row = (size_t)(m0 + ty * 4 + i);
        float q[4], k[4], v[4];
        upk(acc2[i][0], q[0], q[1]); upk(acc2[i][1], q[2], q[3]);
        upk(acc2[i][2], k[0], k[1]); upk(acc2[i][3], k[2], k[3]);
        upk(acc2[i][4], v[0], v[1]); upk(acc2[i][5], v[2], v[3]);
#pragma unroll
        for (int j = 0; j < 4; j++) {
            int a = tx * 4 + j;
            float qf = q[j], kf = k[j] * LOG2E;
            __half qh = __float2half(qf);
            __half kh = __float2half(kf);
            size_t ri = row * AA + a;
            g_qhi[ri] = qh;
            g_qlo[ri] = __float2half(qf - __half2float(qh));
            g_khi[ri] = kh;
            g_klo[ri] = __float2half(kf - __half2float(kh));
            g_vhi[ri] = __float2half(v[j]);
        }
    }
}

// ---------------------------------------------------------------------------
// Kernel 2: causal flash attention, fp16 mma.sync, N-split warp layout.
// 256 CTAs x 256 threads (8 warps). Warp (wr = w&3, wc = w>>2):
// rows wr*16..+15, k-column half wc*32..+31. Row max/sum merged between
// column-half partners via smem; O partials added in epilogue.
// ---------------------------------------------------------------------------
#define SM_QH  0
#define SM_QL  8192
#define SM_KH  16384   // 2 bufs x 8KB (reused as O staging in epilogue)
#define SM_KL  32768
#define SM_VH  49152
#define SM_RED 65536   // max [2][64] f32 @ +0 ; sum [2][64] @ +512
#define SM_TOTAL 66560

extern __shared__ char smc[];

__device__ __forceinline__ void prefetch_kv(uint32_t sb, int buf, size_t gkb, int t)
{
#pragma unroll
    for (int i = 0; i < 2; i++) {
        int idx = t + i * 256;          // 0..511
        int r  = idx >> 3;
        int c4 = idx & 7;
        size_t g = gkb + (size_t)r * AA + c4 * 8;
        uint32_t so = (uint32_t)(buf * 8192 + SWZI(r, c4));
        CP16(sb + SM_KH + so, g_khi + g);
        CP16(sb + SM_KL + so, g_klo + g);
        CP16(sb + SM_VH + so, g_vhi + g);
    }
}

__global__ __launch_bounds__(256, 2) void attn_kernel(float* __restrict__ out)
{
    const uint32_t sb = smem_u32(smc);
    const int t    = threadIdx.x;
    const int w    = t >> 5;
    const int lane = t & 31;
    const int wr   = w & 3;      // row group
    const int wc   = w >> 2;     // k-column half

    // bid -> (tile, b): SM-pair (bid, bid+148) loads sum to 65 or 55 steps;
    // single-CTA SMs (bids 108..147) get mid tiles.
    const int bid = blockIdx.x;
    int tile, b;
    if (bid < 56)       { tile = bid >> 2;              b = bid & 3; }
    else if (bid < 108) { tile = 14 + ((bid - 56) >> 2); b = (bid - 56) & 3; }
    else if (bid < 148) { tile = 40 + ((bid - 108) >> 2); b = (bid - 108) & 3; }
    else if (bid < 204) { tile = 63 - ((bid - 148) >> 2); b = (bid - 148) & 3; }
    else                { tile = 39 - ((bid - 204) >> 2); b = (bid - 204) & 3; }

    const size_t gbase = (size_t)b * LL * AA;
    const int rb = tile * 64 + wr * 16;

    prefetch_kv(sb, 0, gbase, t);
    CP_COMMIT();

    // Load Q tile (64 rows x 64 fp16, hi+lo).
#pragma unroll
    for (int i = 0; i < 2; i++) {
        int idx = t + i * 256;
        int r  = idx >> 3;
        int c4 = idx & 7;
        size_t g = gbase + (size_t)(tile * 64 + r) * AA + c4 * 8;
        int so = SWZI(r, c4);
        *(uint4*)(smc + SM_QH + so) = *(const uint4*)&g_qhi[g];
        *(uint4*)(smc + SM_QL + so) = *(const uint4*)&g_qlo[g];
    }

    float O[8][4];
    float mr[2], lr[2];
    mr[0] = mr[1] = -INFF;
    lr[0] = lr[1] = 0.f;
#pragma unroll
    for (int nt = 0; nt < 8; nt++)
#pragma unroll
        for (int e = 0; e < 4; e++) O[nt][e] = 0.f;

    const int g  = lane >> 2;
    const int tq = lane & 3;
    float* redmax = (float*)(smc + SM_RED);
    float* redsum = (float*)(smc + SM_RED + 512);

    for (int jt = 0; jt <= tile; jt++) {
        const int buf = jt & 1;
        CP_WAIT0();
        __syncthreads();   // KV visible; prior step's smem reads done
        if (jt < tile) {
            prefetch_kv(sb, buf ^ 1, gbase + (size_t)(jt + 1) * 64 * AA, t);
            CP_COMMIT();
        }
        const int kb = jt * 64;
        const bool diag = (jt == tile);

        float S[4][4];
#pragma unroll
        for (int nt = 0; nt < 4; nt++)
#pragma unroll
            for (int e = 0; e < 4; e++) S[nt][e] = 0.f;

        const uint32_t khb = sb + SM_KH + buf * 8192;
        const uint32_t klb = sb + SM_KL + buf * 8192;

        // ---- S = Q K^T over this warp's 32 k-cols (3 split passes) ----
#pragma unroll
        for (int kt = 0; kt < 4; kt++) {
            unsigned qh4[4], ql4[4];
            uint32_t qa = sb + SM_QH +
                SWZI(wr * 16 + (lane & 15), kt * 2 + (lane >> 4));
            ldsm4(qh4, qa);
            ldsm4(ql4, qa + 8192);
#pragma unroll
            for (int np = 0; np < 2; np++) {
                int r  = wc * 32 + np * 16 + ((lane >> 4) << 3) + (lane & 7);
                int c4 = kt * 2 + ((lane >> 3) & 1);
                unsigned kh4[4], kl4[4];
                ldsm4(kh4, khb + SWZI(r, c4));
                ldsm4(kl4, klb + SWZI(r, c4));
#pragma unroll
                for (int ntl = 0; ntl < 2; ntl++)
                    mma16816(S[2 * np + ntl], qh4, kh4 + 2 * ntl);
#pragma unroll
                for (int ntl = 0; ntl < 2; ntl++)
                    mma16816(S[2 * np + ntl], ql4, kh4 + 2 * ntl);
#pragma unroll
                for (int ntl = 0; ntl < 2; ntl++)
                    mma16816(S[2 * np + ntl], qh4, kl4 + 2 * ntl);
            }
        }

        // ---- mask + own-warp row max ----
        int r0 = rb + g, r1 = r0 + 8;
        if (diag) {
#pragma unroll
            for (int nt = 0; nt < 4; nt++) {
                int col = kb + wc * 32 + nt * 8 + 2 * tq;
                if (col     > r0) S[nt][0] = -INFF;
                if (col + 1 > r0) S[nt][1] = -INFF;
                if (col     > r1) S[nt][2] = -INFF;
                if (col + 1 > r1) S[nt][3] = -INFF;
            }
        }
        float m0 = -INFF, m1 = -INFF;
#pragma unroll
        for (int nt = 0; nt < 4; nt++) {
            m0 = fmaxf(m0, fmaxf(S[nt][0], S[nt][1]));
            m1 = fmaxf(m1, fmaxf(S[nt][2], S[nt][3]));
        }
        m0 = fmaxf(m0, __shfl_xor_sync(0xffffffffu, m0, 1));
        m0 = fmaxf(m0, __shfl_xor_sync(0xffffffffu, m0, 2));
        m1 = fmaxf(m1, __shfl_xor_sync(0xffffffffu, m1, 1));
        m1 = fmaxf(m1, __shfl_xor_sync(0xffffffffu, m1, 2));

        if (tq == 0) {
            redmax[wc * 64 + wr * 16 + g]     = m0;
            redmax[wc * 64 + wr * 16 + g + 8] = m1;
        }
        __syncthreads();
        m0 = fmaxf(m0, redmax[(wc ^ 1) * 64 + wr * 16 + g]);
        m1 = fmaxf(m1, redmax[(wc ^ 1) * 64 + wr * 16 + g + 8]);

        float mn0 = fmaxf(mr[0], m0), mn1 = fmaxf(mr[1], m1);
        float sc0 = ex2f(mr[0] - mn0), sc1 = ex2f(mr[1] - mn1);
        mr[0] = mn0; mr[1] = mn1;
#pragma unroll
        for (int nt = 0; nt < 8; nt++) {
            O[nt][0] *= sc0; O[nt][1] *= sc0;
            O[nt][2] *= sc1; O[nt][3] *= sc1;
        }

        // ---- exp + own-warp row sums (write partials), then PV ----
        float rs0 = 0.f, rs1 = 0.f;
#pragma unroll
        for (int nt = 0; nt < 4; nt++) {
            S[nt][0] = ex2f(S[nt][0] - mn0);
            S[nt][1] = ex2f(S[nt][1] - mn0);
            S[nt][2] = ex2f(S[nt][2] - mn1);
            S[nt][3] = ex2f(S[nt][3] - mn1);
            rs0 += S[nt][0] + S[nt][1];
            rs1 += S[nt][2] + S[nt][3];
        }
        rs0 += __shfl_xor_sync(0xffffffffu, rs0, 1);
        rs0 += __shfl_xor_sync(0xffffffffu, rs0, 2);
        rs1 += __shfl_xor_sync(0xffffffffu, rs1, 1);
        rs1 += __shfl_xor_sync(0xffffffffu, rs1, 2);
        if (tq == 0) {
            redsum[wc * 64 + wr * 16 + g]     = rs0;
            redsum[wc * 64 + wr * 16 + g + 8] = rs1;
        }
        __syncthreads();

        // ---- O += P V (P split in regs, V single fp16) ----
        const uint32_t vhb = sb + SM_VH + buf * 8192;
#pragma unroll
        for (int ktp = 0; ktp < 2; ktp++) {
            unsigned ph[4], pl[4];
            ph[0] = pkhl(S[2*ktp  ][0], S[2*ktp  ][1], pl[0]);
            ph[1] = pkhl(S[2*ktp  ][2], S[2*ktp  ][3], pl[1]);
            ph[2] = pkhl(S[2*ktp+1][0], S[2*ktp+1][1], pl[2]);
            ph[3] = pkhl(S[2*ktp+1][2], S[2*ktp+1][3], pl[3]);
#pragma unroll
            for (int np = 0; np < 4; np++) {
                int r  = wc * 32 + ktp * 16 + (((lane >> 3) & 1) << 3) + (lane & 7);
                int c4 = np * 2 + (lane >> 4);
                unsigned vh4[4];
                ldsm4t(vh4, vhb + SWZI(r, c4));
#pragma unroll
                for (int ntl = 0; ntl < 2; ntl++)
                    mma16816(O[2 * np + ntl], ph, vh4 + 2 * ntl);
#pragma unroll
                for (int ntl = 0; ntl < 2; ntl++)
                    mma16816(O[2 * np + ntl], pl, vh4 + 2 * ntl);
            }
        }

        // ---- merged l update ----
        float prs0 = redsum[(wc ^ 1) * 64 + wr * 16 + g];
        float prs1 = redsum[(wc ^ 1) * 64 + wr * 16 + g + 8];
        lr[0] = lr[0] * sc0 + rs0 + prs0;
        lr[1] = lr[1] * sc1 + rs1 + prs1;
    }

    // ---- epilogue: add O partials across column halves, normalize, store ----
    __syncthreads();   // all warps done with KV smem (incl. final S reads)
    if (wc == 1) {
        float* stg = (float*)(smc + SM_KH) + wr * 1024;   // 16x64 f32
#pragma unroll
        for (int nt = 0; nt < 8; nt++) {
            int c = nt * 8 + 2 * tq;
            *(float2*)&stg[g * 64 + c]       = make_float2(O[nt][0], O[nt][1]);
            *(float2*)&stg[(g + 8) * 64 + c] = make_float2(O[nt][2], O[nt][3]);
        }
    }
    __syncthreads();
    if (wc == 0) {
        const float* stg = (const float*)(smc + SM_KH) + wr * 1024;
        float i0 = 1.f / lr[0], i1 = 1.f / lr[1];
        size_t r0 = (size_t)(rb + g), r1 = r0 + 8;
#pragma unroll
        for (int nt = 0; nt < 8; nt++) {
            int c = nt * 8 + 2 * tq;
            float2 p0 = *(const float2*)&stg[g * 64 + c];
            float2 p1 = *(const float2*)&stg[(g + 8) * 64 + c];
            *(float2*)&out[gbase + r0 * AA + c] =
                make_float2((O[nt][0] + p0.x) * i0, (O[nt][1] + p0.y) * i0);
            *(float2*)&out[gbase + r1 * AA + c] =
                make_float2((O[nt][2] + p1.x) * i1, (O[nt][3] + p1.y) * i1);
        }
    }
}

// ---------------------------------------------------------------------------
extern "C" void kernel_launch(void* const* d_in, const int* in_sizes, int n_in,
                              void* d_out, int out_size)
{
    const float* x  = (const float*)d_in[0];
    const float* Wq = (const float*)d_in[1];
    const float* Wk = (const float*)d_in[2];
    const float* Wv = (const float*)d_in[3];
    float* out = (float*)d_out;

    qkv_proj_kernel<<<BB * LL / 64, 256>>>(x, Wq, Wk, Wv);

    cudaFuncSetAttribute(attn_kernel,
                         cudaFuncAttributeMaxDynamicSharedMemorySize, SM_TOTAL);
    attn_kernel<<<256, 256, SM_TOTAL>>>(out);
}

// round 10
// speedup vs baseline: 1.2861x; 1.0381x over previous
#include <cuda_runtime.h>
#include <cuda_fp16.h>
#include <stdint.h>

#define BB 4
#define LL 4096
#define DD 256
#define AA 64
#define INFF 1e30f
#define LOG2E 1.4426950408889634f

typedef unsigned long long ull;

// ------------------------- fp16 split scratch ------------------------------
__device__ __align__(256) __half g_qhi[BB * LL * AA];
__device__ __align__(256) __half g_qlo[BB * LL * AA];
__device__ __align__(256) __half g_khi[BB * LL * AA];  // pre-scaled by log2e
__device__ __align__(256) __half g_klo[BB * LL * AA];
__device__ __align__(256) __half g_vhi[BB * LL * AA];  // single fp16

// ------------------------- PTX helpers -------------------------------------
__device__ __forceinline__ uint32_t smem_u32(const void* p) {
    uint32_t a;
    asm("{ .reg .u64 t; cvta.to.shared.u64 t, %1; cvt.u32.u64 %0, t; }"
        : "=r"(a) : "l"(p));
    return a;
}

#define SWZI(r, c4) (((r) << 7) + ((((c4) ^ ((r) & 7))) << 4))

__device__ __forceinline__ void ldsm4(unsigned r[4], uint32_t a) {
    asm volatile("ldmatrix.sync.aligned.m8n8.x4.shared.b16 {%0,%1,%2,%3}, [%4];"
        : "=r"(r[0]), "=r"(r[1]), "=r"(r[2]), "=r"(r[3]) : "r"(a));
}
__device__ __forceinline__ void ldsm4t(unsigned r[4], uint32_t a) {
    asm volatile("ldmatrix.sync.aligned.m8n8.x4.trans.shared.b16 {%0,%1,%2,%3}, [%4];"
        : "=r"(r[0]), "=r"(r[1]), "=r"(r[2]), "=r"(r[3]) : "r"(a));
}
__device__ __forceinline__ void mma16816(float d[4], const unsigned a[4],
                                         const unsigned b[2]) {
    asm volatile("mma.sync.aligned.m16n8k16.row.col.f32.f16.f16.f32 "
        "{%0,%1,%2,%3}, {%4,%5,%6,%7}, {%8,%9}, {%0,%1,%2,%3};"
        : "+f"(d[0]), "+f"(d[1]), "+f"(d[2]), "+f"(d[3])
        : "r"(a[0]), "r"(a[1]), "r"(a[2]), "r"(a[3]), "r"(b[0]), "r"(b[1]));
}
#define CP16(d, s) asm volatile("cp.async.cg.shared.global [%0], [%1], 16;" :: "r"(d), "l"(s))
#define CP_COMMIT() asm volatile("cp.async.commit_group;" ::: "memory")
#define CP_WAIT0()  asm volatile("cp.async.wait_group 0;" ::: "memory")

__device__ __forceinline__ float ex2f(float x) {
    float r;
    asm("ex2.approx.ftz.f32 %0, %1;" : "=f"(r) : "f"(x));
    return r;
}
__device__ __forceinline__ ull pk2(float a) {
    ull r; unsigned u = __float_as_uint(a);
    asm("mov.b64 %0, {%1, %1};" : "=l"(r) : "r"(u));
    return r;
}
__device__ __forceinline__ void fma2(ull& d, ull a, ull b) {
    asm("fma.rn.f32x2 %0, %1, %2, %0;" : "+l"(d) : "l"(a), "l"(b));
}
__device__ __forceinline__ void upk(ull v, float& x, float& y) {
    unsigned a, b;
    asm("mov.b64 {%0, %1}, %2;" : "=r"(a), "=r"(b) : "l"(v));
    x = __uint_as_float(a); y = __uint_as_float(b);
}
// pack hi fp16x2, return lo residual fp16x2 via out-param
__device__ __forceinline__ unsigned pkhl(float a, float b, unsigned& lo) {
    __half2 h2 = __floats2half2_rn(a, b);
    float2 hf = __half22float2(h2);
    __half2 l2 = __floats2half2_rn(a - hf.x, b - hf.y);
    lo = *(unsigned*)&l2;
    return *(unsigned*)&h2;
}

// ---------------------------------------------------------------------------
// Kernel 1: fused QKV projection (f32x2 inner loop) -> fp16 splits.
// (R7 version: measured-good.)
// ---------------------------------------------------------------------------
__global__ __launch_bounds__(256) void qkv_proj_kernel(
    const float* __restrict__ x,
    const float* __restrict__ Wq,
    const float* __restrict__ Wk,
    const float* __restrict__ Wv)
{
    __shared__ float xs[32 * 65];
    __shared__ float ws[32 * 196];

    const int t  = threadIdx.x;
    const int ty = t >> 4;
    const int tx = t & 15;
    const int m0 = blockIdx.x * 64;

    ull acc2[4][6];
#pragma unroll
    for (int i = 0; i < 4; i++)
#pragma unroll
        for (int j = 0; j < 6; j++) acc2[i][j] = 0ull;

    for (int d0 = 0; d0 < DD; d0 += 32) {
#pragma unroll
        for (int i = 0; i < 8; i++) {
            int idx = t + i * 256;
            int m = idx >> 5;
            int d = idx & 31;
            xs[d * 65 + m] = x[(size_t)(m0 + m) * DD + d0 + d];
        }
#pragma unroll
        for (int i = 0; i < 6; i++) {
            int idx = t + i * 256;
            int mat = idx >> 9;
            int r   = idx & 511;
            int d   = r >> 4;
            int a4  = r & 15;
            const float* W = (mat == 0) ? Wq : (mat == 1) ? Wk : Wv;
            *(float4*)&ws[d * 196 + mat * 64 + a4 * 4] =
                *(const float4*)&W[(size_t)(d0 + d) * AA + a4 * 4];
        }
        __syncthreads();

#pragma unroll
        for (int d = 0; d < 32; d++) {
            ull ap[4];
#pragma unroll
            for (int i = 0; i < 4; i++) ap[i] = pk2(xs[d * 65 + ty * 4 + i]);
            const ull* bq = (const ull*)&ws[d * 196 +       tx * 4];
            const ull* bk = (const ull*)&ws[d * 196 +  64 + tx * 4];
            const ull* bv = (const ull*)&ws[d * 196 + 128 + tx * 4];
            ull q0 = bq[0], q1 = bq[1];
            ull k0 = bk[0], k1 = bk[1];
            ull v0 = bv[0], v1 = bv[1];
#pragma unroll
            for (int i = 0; i < 4; i++) {
                fma2(acc2[i][0], ap[i], q0); fma2(acc2[i][1], ap[i], q1);
                fma2(acc2[i][2], ap[i], k0); fma2(acc2[i][3], ap[i], k1);
                fma2(acc2[i][4], ap[i], v0); fma2(acc2[i][5], ap[i], v1);
            }
        }
        __syncthreads();
    }

#pragma unroll
    for (int i = 0; i < 4; i++) {
        size_t row = (size_t)(m0 + ty * 4 + i);
        float q[4], k[4], v[4];
        upk(acc2[i][0], q[0], q[1]); upk(acc2[i][1], q[2], q[3]);
        upk(acc2[i][2], k[0], k[1]); upk(acc2[i][3], k[2], k[3]);
        upk(acc2[i][4], v[0], v[1]); upk(acc2[i][5], v[2], v[3]);
#pragma unroll
        for (int j = 0; j < 4; j++) {
            int a = tx * 4 + j;
            float qf = q[j], kf = k[j] * LOG2E;
            __half qh = __float2half(qf);
            __half kh = __float2half(kf);
            size_t ri = row * AA + a;
            g_qhi[ri] = qh;
            g_qlo[ri] = __float2half(qf - __half2float(qh));
            g_khi[ri] = kh;
            g_klo[ri] = __float2half(kf - __half2float(kh));
            g_vhi[ri] = __float2half(v[j]);
        }
    }
}

// ---------------------------------------------------------------------------
// Kernel 2: causal flash attention, fp16 mma.sync (R7 shape: 128 thr, 4 warps,
// 2 CTA/SM). NEW: per kt, all 4 np fragments are loaded first and MMAs issue
// pass-outermost / np-inner, so same-accumulator MMAs are 8 issues apart
// (> HMMA RAW latency) instead of 2.
// ---------------------------------------------------------------------------
#define SM_QH  0
#define SM_QL  8192
#define SM_KH  16384   // 2 bufs x 8KB
#define SM_KL  32768
#define SM_VH  49152
#define SM_TOTAL 65536

extern __shared__ char smc[];

__device__ __forceinline__ void prefetch_kv(uint32_t sb, int buf, size_t gkb, int t)
{
#pragma unroll
    for (int i = 0; i < 4; i++) {
        int idx = t + i * 128;          // 0..511
        int r  = idx >> 3;
        int c4 = idx & 7;
        size_t g = gkb + (size_t)r * AA + c4 * 8;
        uint32_t so = (uint32_t)(buf * 8192 + SWZI(r, c4));
        CP16(sb + SM_KH + so, g_khi + g);
        CP16(sb + SM_KL + so, g_klo + g);
        CP16(sb + SM_VH + so, g_vhi + g);
    }
}

__global__ __launch_bounds__(128, 2) void attn_kernel(float* __restrict__ out)
{
    const uint32_t sb = smem_u32(smc);
    const int t    = threadIdx.x;
    const int w    = t >> 5;
    const int lane = t & 31;

    // bid -> (tile, b): SM-pair (bid, bid+148) loads sum to 65 or 55 steps;
    // single-CTA SMs (bids 108..147) get mid tiles.
    const int bid = blockIdx.x;
    int tile, b;
    if (bid < 56)       { tile = bid >> 2;              b = bid & 3; }
    else if (bid < 108) { tile = 14 + ((bid - 56) >> 2); b = (bid - 56) & 3; }
    else if (bid < 148) { tile = 40 + ((bid - 108) >> 2); b = (bid - 108) & 3; }
    else if (bid < 204) { tile = 63 - ((bid - 148) >> 2); b = (bid - 148) & 3; }
    else                { tile = 39 - ((bid - 204) >> 2); b = (bid - 204) & 3; }

    const size_t gbase = (size_t)b * LL * AA;
    const int rb = tile * 64 + w * 16;

    prefetch_kv(sb, 0, gbase, t);
    CP_COMMIT();

    // Load Q tile (64 rows x 64 fp16, hi+lo).
#pragma unroll
    for (int i = 0; i < 4; i++) {
        int idx = t + i * 128;
        int r  = idx >> 3;
        int c4 = idx & 7;
        size_t g = gbase + (size_t)(tile * 64 + r) * AA + c4 * 8;
        int so = SWZI(r, c4);
        *(uint4*)(smc + SM_QH + so) = *(const uint4*)&g_qhi[g];
        *(uint4*)(smc + SM_QL + so) = *(const uint4*)&g_qlo[g];
    }

    float O[8][4];
    float mr[2], lr[2];
    mr[0] = mr[1] = -INFF;
    lr[0] = lr[1] = 0.f;
#pragma unroll
    for (int nt = 0; nt < 8; nt++)
#pragma unroll
        for (int e = 0; e < 4; e++) O[nt][e] = 0.f;

    const int g  = lane >> 2;
    const int tq = lane & 3;

    for (int jt = 0; jt <= tile; jt++) {
        const int buf = jt & 1;
        CP_WAIT0();
        __syncthreads();
        if (jt < tile) {
            prefetch_kv(sb, buf ^ 1, gbase + (size_t)(jt + 1) * 64 * AA, t);
            CP_COMMIT();
        }
        const int kb = jt * 64;
        const bool diag = (jt == tile);

        float S[8][4];
#pragma unroll
        for (int nt = 0; nt < 8; nt++)
#pragma unroll
            for (int e = 0; e < 4; e++) S[nt][e] = 0.f;

        const uint32_t khb = sb + SM_KH + buf * 8192;
        const uint32_t klb = sb + SM_KL + buf * 8192;

        // ---- S = Q K^T: batch-load all np fragments, pass-outermost MMAs ----
#pragma unroll
        for (int kt = 0; kt < 4; kt++) {
            unsigned qh4[4], ql4[4];
            uint32_t qa = sb + SM_QH +
                SWZI(w * 16 + (lane & 15), kt * 2 + (lane >> 4));
            ldsm4(qh4, qa);
            ldsm4(ql4, qa + 8192);
            unsigned kh4[4][4], kl4[4][4];
#pragma unroll
            for (int np = 0; np < 4; np++) {
                int r  = np * 16 + ((lane >> 4) << 3) + (lane & 7);
                int c4 = kt * 2 + ((lane >> 3) & 1);
                ldsm4(kh4[np], khb + SWZI(r, c4));
                ldsm4(kl4[np], klb + SWZI(r, c4));
            }
            // pass 1: qh * kh — touches all 8 accumulators
#pragma unroll
            for (int np = 0; np < 4; np++)
#pragma unroll
                for (int ntl = 0; ntl < 2; ntl++)
                    mma16816(S[2 * np + ntl], qh4, kh4[np] + 2 * ntl);
            // pass 2: ql * kh
#pragma unroll
            for (int np = 0; np < 4; np++)
#pragma unroll
                for (int ntl = 0; ntl < 2; ntl++)
                    mma16816(S[2 * np + ntl], ql4, kh4[np] + 2 * ntl);
            // pass 3: qh * kl
#pragma unroll
            for (int np = 0; np < 4; np++)
#pragma unroll
                for (int ntl = 0; ntl < 2; ntl++)
                    mma16816(S[2 * np + ntl], qh4, kl4[np] + 2 * ntl);
        }

        // ---- mask + row max + O rescale ----
        int r0 = rb + g, r1 = r0 + 8;
        if (diag) {
#pragma unroll
            for (int nt = 0; nt < 8; nt++) {
                int col = kb + nt * 8 + 2 * tq;
                if (col     > r0) S[nt][0] = -INFF;
                if (col + 1 > r0) S[nt][1] = -INFF;
                if (col     > r1) S[nt][2] = -INFF;
                if (col + 1 > r1) S[nt][3] = -INFF;
            }
        }
        float m0 = -INFF, m1 = -INFF;
#pragma unroll
        for (int nt = 0; nt < 8; nt++) {
            m0 = fmaxf(m0, fmaxf(S[nt][0], S[nt][1]));
            m1 = fmaxf(m1, fmaxf(S[nt][2], S[nt][3]));
        }
        m0 = fmaxf(m0, __shfl_xor_sync(0xffffffffu, m0, 1));
        m0 = fmaxf(m0, __shfl_xor_sync(0xffffffffu, m0, 2));
        m1 = fmaxf(m1, __shfl_xor_sync(0xffffffffu, m1, 1));
        m1 = fmaxf(m1, __shfl_xor_sync(0xffffffffu, m1, 2));
        float mn0 = fmaxf(mr[0], m0), mn1 = fmaxf(mr[1], m1);
        float sc0 = ex2f(mr[0] - mn0), sc1 = ex2f(mr[1] - mn1);
        mr[0] = mn0; mr[1] = mn1;
#pragma unroll
        for (int nt = 0; nt < 8; nt++) {
            O[nt][0] *= sc0; O[nt][1] *= sc0;
            O[nt][2] *= sc1; O[nt][3] *= sc1;
        }

        // ---- exp/pack + PV: batch-load V fragments, pass-outermost MMAs ----
        const uint32_t vhb = sb + SM_VH + buf * 8192;
        float rs0 = 0.f, rs1 = 0.f;
#pragma unroll
        for (int kt = 0; kt < 4; kt++) {
            unsigned ph[4], pl[4];
            {
                float e00 = ex2f(S[2*kt  ][0] - mn0);
                float e01 = ex2f(S[2*kt  ][1] - mn0);
                float e02 = ex2f(S[2*kt  ][2] - mn1);
                float e03 = ex2f(S[2*kt  ][3] - mn1);
                float e10 = ex2f(S[2*kt+1][0] - mn0);
                float e11 = ex2f(S[2*kt+1][1] - mn0);
                float e12 = ex2f(S[2*kt+1][2] - mn1);
                float e13 = ex2f(S[2*kt+1][3] - mn1);
                rs0 += (e00 + e01) + (e10 + e11);
                rs1 += (e02 + e03) + (e12 + e13);
                ph[0] = pkhl(e00, e01, pl[0]);
                ph[1] = pkhl(e02, e03, pl[1]);
                ph[2] = pkhl(e10, e11, pl[2]);
                ph[3] = pkhl(e12, e13, pl[3]);
            }
            unsigned vh4[4][4];
#pragma unroll
            for (int np = 0; np < 4; np++) {
                int r  = kt * 16 + (((lane >> 3) & 1) << 3) + (lane & 7);
                int c4 = np * 2 + (lane >> 4);
                ldsm4t(vh4[np], vhb + SWZI(r, c4));
            }
            // pass 1: ph * v — touches all 8 accumulators
#pragma unroll
            for (int np = 0; np < 4; np++)
#pragma unroll
                for (int ntl = 0; ntl < 2; ntl++)
                    mma16816(O[2 * np + ntl], ph, vh4[np] + 2 * ntl);
            // pass 2: pl * v
#pragma unroll
            for (int np = 0; np < 4; np++)
#pragma unroll
                for (int ntl = 0; ntl < 2; ntl++)
                    mma16816(O[2 * np + ntl], pl, vh4[np] + 2 * ntl);
        }

        rs0 += __shfl_xor_sync(0xffffffffu, rs0, 1);
        rs0 += __shfl_xor_sync(0xffffffffu, rs0, 2);
        rs1 += __shfl_xor_sync(0xffffffffu, rs1, 1);
        rs1 += __shfl_xor_sync(0xffffffffu, rs1, 2);
        lr[0] = lr[0] * sc0 + rs0;
        lr[1] = lr[1] * sc1 + rs1;

        __syncthreads();
    }

    // ---- epilogue ----
    float i0 = 1.f / lr[0], i1 = 1.f / lr[1];
    size_t r0 = (size_t)(rb + g), r1 = r0 + 8;
#pragma unroll
    for (int nt = 0; nt < 8; nt++) {
        *(float2*)&out[gbase + r0 * AA + nt * 8 + 2 * tq] =
            make_float2(O[nt][0] * i0, O[nt][1] * i0);
        *(float2*)&out[gbase + r1 * AA + nt * 8 + 2 * tq] =
            make_float2(O[nt][2] * i1, O[nt][3] * i1);
    }
}

// ---------------------------------------------------------------------------
extern "C" void kernel_launch(void* const* d_in, const int* in_sizes, int n_in,
                              void* d_out, int out_size)
{
    const float* x  = (const float*)d_in[0];
    const float* Wq = (const float*)d_in[1];
    const float* Wk = (const float*)d_in[2];
    const float* Wv = (const float*)d_in[3];
    float* out = (float*)d_out;

    qkv_proj_kernel<<<BB * LL / 64, 256>>>(x, Wq, Wk, Wv);

    cudaFuncSetAttribute(attn_kernel,
                         cudaFuncAttributeMaxDynamicSharedMemorySize, SM_TOTAL);
    attn_kernel<<<256, 128, SM_TOTAL>>>(out);
}